// round 11
// baseline (speedup 1.0000x reference)
#include <cuda_runtime.h>
#include <cstdint>

// ---------------------------------------------------------------------------
// MyModel_87522843559014: LSTM(B=256,T=512,F=128,H=256) + MLP head
//   reset -> xz_gemm -> dummy -> lstm (ncu captures 4th launch) -> head
//   lstm: 16 clusters x 8 CTAs. mma.sync m16n8k8 tf32, A in registers.
//   R11: h exchange via DSMEM — producers write tf32 fragments straight into
//   all 8 CTAs' B-buffers (mapa + st.shared::cluster), sync via mbarriers
//   (release/acquire.cluster). No global flags, no L2 round trips in loop.
// ---------------------------------------------------------------------------

typedef unsigned long long ull;

__device__ float g_xz[512u * 256u * 1024u];   // [T][B][4H] fp32
__device__ float g_h[2][256][256];            // final h only (head input)
__device__ unsigned g_flag[16 * 8 * 32];      // legacy (reset keeps launch count)

__global__ void reset_kernel() {
    if (threadIdx.x < 128) g_flag[threadIdx.x * 32] = 0u;
}
__global__ void dummy_kernel() {}

// ---------------- f32x2 helpers (xz gemm) -------------------------------------
__device__ __forceinline__ ull fma2(ull a, ull b, ull c) {
    ull d;
    asm("fma.rn.f32x2 %0, %1, %2, %3;" : "=l"(d) : "l"(a), "l"(b), "l"(c));
    return d;
}
__device__ __forceinline__ ull dup2(float x) {
    ull r;
    asm("mov.b64 %0, {%1, %1};" : "=l"(r) : "f"(x));
    return r;
}
__device__ __forceinline__ float lo32(ull v) { return __uint_as_float((unsigned)v); }
__device__ __forceinline__ float hi32(ull v) { return __uint_as_float((unsigned)(v >> 32)); }

// ---------------- input projection GEMM (f32x2, unchanged) --------------------
__global__ void __launch_bounds__(256, 2)
xz_gemm_kernel(const float* __restrict__ x, const float* __restrict__ kern) {
    __shared__ float As[8][132];
    __shared__ float Bs[8][132];

    const int tid = threadIdx.x;
    const int nb = blockIdx.x;
    const int mb = blockIdx.y;
    const int m0 = mb * 128, n0 = nb * 128;

    const int lrow = tid >> 1;
    const int lk4  = (tid & 1) * 4;
    const int m    = m0 + lrow;
    const int tt   = m >> 8;
    const int bb   = m & 255;
    const float* xrow = x + ((size_t)bb * 512 + tt) * 128;

    const int bk = tid >> 5;
    const int bn = (tid & 31) * 4;

    const int tm = (tid >> 4) * 8;
    const int tn = (tid & 15) * 8;

    ull acc2[4][8];
#pragma unroll
    for (int i = 0; i < 4; i++)
#pragma unroll
        for (int j = 0; j < 8; j++) acc2[i][j] = 0ull;

    for (int k0 = 0; k0 < 128; k0 += 8) {
        float4 av = *(const float4*)(xrow + k0 + lk4);
        float4 bv = *(const float4*)(kern + (size_t)(k0 + bk) * 1024 + n0 + bn);
        __syncthreads();
        As[lk4 + 0][lrow] = av.x;
        As[lk4 + 1][lrow] = av.y;
        As[lk4 + 2][lrow] = av.z;
        As[lk4 + 3][lrow] = av.w;
        *(float4*)&Bs[bk][bn] = bv;
        __syncthreads();
#pragma unroll
        for (int kk = 0; kk < 8; kk++) {
            ulonglong2 a0 = *(const ulonglong2*)&As[kk][tm];
            ulonglong2 a1 = *(const ulonglong2*)&As[kk][tm + 4];
            ull ap[4] = {a0.x, a0.y, a1.x, a1.y};
            float4 b0 = *(const float4*)&Bs[kk][tn];
            float4 b1 = *(const float4*)&Bs[kk][tn + 4];
            {
                ull bd0 = dup2(b0.x), bd1 = dup2(b0.y), bd2 = dup2(b0.z), bd3 = dup2(b0.w);
#pragma unroll
                for (int i = 0; i < 4; i++) {
                    acc2[i][0] = fma2(ap[i], bd0, acc2[i][0]);
                    acc2[i][1] = fma2(ap[i], bd1, acc2[i][1]);
                    acc2[i][2] = fma2(ap[i], bd2, acc2[i][2]);
                    acc2[i][3] = fma2(ap[i], bd3, acc2[i][3]);
                }
            }
            {
                ull bd4 = dup2(b1.x), bd5 = dup2(b1.y), bd6 = dup2(b1.z), bd7 = dup2(b1.w);
#pragma unroll
                for (int i = 0; i < 4; i++) {
                    acc2[i][4] = fma2(ap[i], bd4, acc2[i][4]);
                    acc2[i][5] = fma2(ap[i], bd5, acc2[i][5]);
                    acc2[i][6] = fma2(ap[i], bd6, acc2[i][6]);
                    acc2[i][7] = fma2(ap[i], bd7, acc2[i][7]);
                }
            }
        }
    }

#pragma unroll
    for (int i2 = 0; i2 < 4; i2++) {
        float* d0 = g_xz + (size_t)(m0 + tm + 2 * i2) * 1024 + n0 + tn;
        float* d1 = d0 + 1024;
        *(float4*)(d0 + 0) = make_float4(lo32(acc2[i2][0]), lo32(acc2[i2][1]),
                                         lo32(acc2[i2][2]), lo32(acc2[i2][3]));
        *(float4*)(d0 + 4) = make_float4(lo32(acc2[i2][4]), lo32(acc2[i2][5]),
                                         lo32(acc2[i2][6]), lo32(acc2[i2][7]));
        *(float4*)(d1 + 0) = make_float4(hi32(acc2[i2][0]), hi32(acc2[i2][1]),
                                         hi32(acc2[i2][2]), hi32(acc2[i2][3]));
        *(float4*)(d1 + 4) = make_float4(hi32(acc2[i2][4]), hi32(acc2[i2][5]),
                                         hi32(acc2[i2][6]), hi32(acc2[i2][7]));
    }
}

// ---------------- fast activations -------------------------------------------
__device__ __forceinline__ float sigf(float x)     { return 1.f / (1.f + __expf(-x)); }
__device__ __forceinline__ float tanhfast(float x) { return 2.f / (1.f + __expf(-2.f * x)) - 1.f; }

// ---------------- tf32 mma helpers --------------------------------------------
__device__ __forceinline__ uint32_t to_tf32(float f) {
    uint32_t u;
    asm("cvt.rna.tf32.f32 %0, %1;" : "=r"(u) : "f"(f));
    return u;
}
__device__ __forceinline__ void mma_tf32(float* c, const uint32_t* a,
                                         const uint32_t* b) {
    asm volatile(
        "mma.sync.aligned.m16n8k8.row.col.f32.tf32.tf32.f32 "
        "{%0,%1,%2,%3}, {%4,%5,%6,%7}, {%8,%9}, {%0,%1,%2,%3};"
        : "+f"(c[0]), "+f"(c[1]), "+f"(c[2]), "+f"(c[3])
        : "r"(a[0]), "r"(a[1]), "r"(a[2]), "r"(a[3]), "r"(b[0]), "r"(b[1]));
}

// ---------------- cluster / mbarrier helpers -----------------------------------
__device__ __forceinline__ uint32_t smem_u32(const void* p) {
    uint32_t a;
    asm("{ .reg .u64 t; cvta.to.shared.u64 t, %1; cvt.u32.u64 %0, t; }"
        : "=r"(a) : "l"(p));
    return a;
}
__device__ __forceinline__ void mbar_init(uint32_t a, uint32_t cnt) {
    asm volatile("mbarrier.init.shared.b64 [%0], %1;" :: "r"(a), "r"(cnt) : "memory");
}
__device__ __forceinline__ void mbar_arrive_rank(uint32_t a, uint32_t rank) {
    asm volatile(
        "{ .reg .b32 ra;\n\t"
        "mapa.shared::cluster.u32 ra, %0, %1;\n\t"
        "mbarrier.arrive.release.cluster.shared::cluster.b64 _, [ra]; }"
        :: "r"(a), "r"(rank) : "memory");
}
__device__ __forceinline__ void mbar_wait(uint32_t a, uint32_t ph) {
    asm volatile(
        "{ .reg .pred P;\n\t"
        "W%=: mbarrier.try_wait.parity.acquire.cluster.shared::cta.b64 P, [%0], %1, 0x989680;\n\t"
        "@P bra D%=;\n\t"
        "bra W%=;\n\t"
        "D%=: }"
        :: "r"(a), "r"(ph) : "memory");
}
__device__ __forceinline__ void sts_cluster_u64(uint32_t a, uint32_t rank, ull v) {
    asm volatile(
        "{ .reg .b32 ra;\n\t"
        "mapa.shared::cluster.u32 ra, %0, %1;\n\t"
        "st.shared::cluster.u64 [ra], %2; }"
        :: "r"(a), "r"(rank), "l"(v) : "memory");
}

// smem layout (bytes). AF staging (131072B) aliases everything; all loop-time
// regions (incl. mbarriers) are initialized AFTER A is copied to registers.
#define SM_BF0   0         // 2048 x uint2 B fragments, buffer 0   16384
#define SM_BF1   16384     // buffer 1                              16384
#define SM_ZS    32768     // 4 x [128][17] f32 partials            34816
#define SM_CS    67584     // [512] f32 cell state                   2048
#define SM_MB    69632     // 2 mbarriers (8B each)
#define SM_TOTAL 131072

// ---------------- persistent LSTM kernel (tf32 mma + DSMEM exchange) ----------
// 16 clusters x 8 CTAs; cluster = batch group (16 batches), CTA jt = rank owns
// gate-cols [jt*32,+32) x 4 gates = 128 M-cols, K=256, N=16.
__global__ void __launch_bounds__(256, 1) __cluster_dims__(8, 1, 1)
lstm_kernel(const float* __restrict__ rkernel) {
    extern __shared__ char smem[];
    uint4*  AF  = (uint4*)(smem);            // staging only (pre-loop)
    float*  zs  = (float*)(smem + SM_ZS);
    float*  c_s = (float*)(smem + SM_CS);
    const uint32_t sbase = smem_u32(smem);
    const uint32_t mb0 = sbase + SM_MB, mb1 = sbase + SM_MB + 8;

    const int tid = threadIdx.x;
    const int wid = tid >> 5, lane = tid & 31;
    const int grp = blockIdx.x >> 3;    // 0..15
    const int jt  = blockIdx.x & 7;     // == cluster rank
    const int bbase = grp * 16, jbase = jt * 32;
    const int gid = lane >> 2, tig = lane & 3;

    // ---- stage A fragments in smem (fragment order), then copy to registers
    for (int idx = tid; idx < 8192; idx += 256) {
        int ln = idx & 31, t2 = idx >> 5;
        int i  = t2 & 3, km = (t2 >> 2) & 7, kqz = (t2 >> 5) & 3, mhz = t2 >> 7;
        int g2 = ln >> 2, t4 = ln & 3;
        int M0 = mhz * 64 + i * 16, K0 = kqz * 64 + km * 8;
        int mr0 = M0 + g2, mr1 = M0 + 8 + g2;
        int col0 = (mr0 >> 5) * 256 + jbase + (mr0 & 31);
        int col1 = (mr1 >> 5) * 256 + jbase + (mr1 & 31);
        uint4 v;
        v.x = to_tf32(rkernel[(K0 + t4) * 1024 + col0]);
        v.y = to_tf32(rkernel[(K0 + t4) * 1024 + col1]);
        v.z = to_tf32(rkernel[(K0 + t4 + 4) * 1024 + col0]);
        v.w = to_tf32(rkernel[(K0 + t4 + 4) * 1024 + col1]);
        AF[idx] = v;
    }
    __syncthreads();

    const int mh = wid >> 2, kq = wid & 3;
    const int Mbase = mh * 64;
    uint4 areg[4][8];
    {
        const uint4* afp = AF + (mh * 4 + kq) * 1024 + lane;
#pragma unroll
        for (int i = 0; i < 4; i++)
#pragma unroll
            for (int km = 0; km < 8; km++)
                areg[i][km] = afp[km * 128 + i * 32];
    }
    __syncthreads();   // AF region now reusable

    // init loop-time smem: BF0 = 0 (h0 = 0), c = 0, mbarriers (count 8)
    for (int i = tid; i < 4096; i += 256)            // BF0 as 4096 u32
        ((uint32_t*)(smem + SM_BF0))[i] = 0u;
    for (int p = tid; p < 512; p += 256) c_s[p] = 0.f;
    if (tid == 0) { mbar_init(mb0, 8u); mbar_init(mb1, 8u); }
    __syncthreads();

    // cluster-wide: all mbarriers/BF0 initialized before any arrivals
    asm volatile("barrier.cluster.arrive.aligned;" ::: "memory");
    asm volatile("barrier.cluster.wait.aligned;" ::: "memory");
    if (tid == 0) {
        asm volatile("fence.acq_rel.cluster;" ::: "memory");
#pragma unroll
        for (int r = 0; r < 8; r++) mbar_arrive_rank(mb0, (uint32_t)r);
    }

    // xz prefetch registers (gate phase): [pp*4 + gate]
    float xzp[8], xzn[8];
#pragma unroll
    for (int pp = 0; pp < 2; pp++) {
        int p = tid + pp * 256;
        int bb = p >> 5, jj = p & 31;
        size_t base = ((size_t)(bbase + bb)) * 1024 + jbase + jj;
#pragma unroll
        for (int g = 0; g < 4; g++) xzp[pp * 4 + g] = __ldcg(&g_xz[base + g * 256]);
    }

    for (int t = 0; t < 512; t++) {
        const int par = t & 1;
        // wait BF[par] full: 8 arrivals (phase parity = (t>>1)&1)
        if (tid == 0) mbar_wait(par ? mb1 : mb0, (uint32_t)((t >> 1) & 1));
        __syncthreads();

        const uint2* bfp = (const uint2*)(smem + (par ? SM_BF1 : SM_BF0))
                           + kq * 512 + lane;

        // 64 MMAs, A operands from registers
        float cacc[4][2][4];
#pragma unroll
        for (int i = 0; i < 4; i++)
#pragma unroll
            for (int j = 0; j < 2; j++)
#pragma unroll
                for (int r = 0; r < 4; r++) cacc[i][j][r] = 0.f;

#pragma unroll
        for (int km = 0; km < 8; km++) {
            uint2 bv0 = bfp[km * 64];
            uint2 bv1 = bfp[km * 64 + 32];
            uint32_t b0[2] = {bv0.x, bv0.y};
            uint32_t b1[2] = {bv1.x, bv1.y};
#pragma unroll
            for (int i = 0; i < 4; i++) {
                uint32_t a[4] = {areg[i][km].x, areg[i][km].y,
                                 areg[i][km].z, areg[i][km].w};
                mma_tf32(cacc[i][0], a, b0);
                mma_tf32(cacc[i][1], a, b1);
            }
        }

        float* zq = zs + kq * (128 * 17);
#pragma unroll
        for (int i = 0; i < 4; i++) {
            int m0 = Mbase + i * 16 + gid;
#pragma unroll
            for (int j = 0; j < 2; j++) {
                int n0 = j * 8 + tig * 2;
                zq[m0 * 17 + n0]           = cacc[i][j][0];
                zq[m0 * 17 + n0 + 1]       = cacc[i][j][1];
                zq[(m0 + 8) * 17 + n0]     = cacc[i][j][2];
                zq[(m0 + 8) * 17 + n0 + 1] = cacc[i][j][3];
            }
        }

        // prefetch next xz (independent of h)
        if (t < 511) {
#pragma unroll
            for (int pp = 0; pp < 2; pp++) {
                int p = tid + pp * 256;
                int bb = p >> 5, jj = p & 31;
                size_t base = ((size_t)((t + 1) * 256 + bbase + bb)) * 1024
                            + jbase + jj;
#pragma unroll
                for (int g = 0; g < 4; g++)
                    xzn[pp * 4 + g] = __ldcg(&g_xz[base + g * 256]);
            }
        }
        __syncthreads();

        // gates: 512 (b,j) pairs, 2 per thread; h -> DSMEM B-frags of all ranks
        const uint32_t bfdst = sbase + (par ? SM_BF0 : SM_BF1);   // buffer par^1
#pragma unroll
        for (int pp = 0; pp < 2; pp++) {
            int p = tid + pp * 256;
            int bb = p >> 5, jj = p & 31;
            float zi = xzp[pp * 4 + 0], zf = xzp[pp * 4 + 1];
            float zg = xzp[pp * 4 + 2], zo = xzp[pp * 4 + 3];
#pragma unroll
            for (int q = 0; q < 4; q++) {
                const float* zb = zs + q * (128 * 17);
                zi += zb[(jj)      * 17 + bb];
                zf += zb[(32 + jj) * 17 + bb];
                zg += zb[(64 + jj) * 17 + bb];
                zo += zb[(96 + jj) * 17 + bb];
            }
            float cn = sigf(zf) * c_s[p] + sigf(zi) * tanhfast(zg);
            c_s[p] = cn;
            float hval = sigf(zo) * tanhfast(cn);

            if (t < 511) {
                uint32_t hv = to_tf32(hval);
                uint32_t pv = __shfl_xor_sync(0xffffffffu, hv, 4);
                uint32_t vlo = (jj & 4) ? pv : hv;
                uint32_t vhi = (jj & 4) ? hv : pv;
                ull pk = (ull)vlo | ((ull)vhi << 32);
                int k = jbase + (jj & ~4);     // k of .x element
                int e = (k >> 6) * 512 + ((k >> 3) & 7) * 64
                      + (bb >> 3) * 32 + (bb & 7) * 4 + (k & 3);
                uint32_t addr = bfdst + (uint32_t)e * 8;
                int r0 = (jj & 4) ? 4 : 0;
#pragma unroll
                for (int r = 0; r < 4; r++)
                    sts_cluster_u64(addr, (uint32_t)(r0 + r), pk);
            } else {
                g_h[0][bbase + bb][jbase + jj] = hval;
            }
        }
#pragma unroll
        for (int r = 0; r < 8; r++) xzp[r] = xzn[r];

        if (t < 511) {
            __syncthreads();   // all remote stores issued by this CTA
            if (tid == 0) {
                asm volatile("fence.acq_rel.cluster;" ::: "memory");
                uint32_t mb = par ? mb0 : mb1;   // barrier of buffer par^1
#pragma unroll
                for (int r = 0; r < 8; r++) mbar_arrive_rank(mb, (uint32_t)r);
            }
        }
    }

    __threadfence();   // final g_h stores visible before kernel end
    asm volatile("barrier.cluster.arrive.aligned;" ::: "memory");
    asm volatile("barrier.cluster.wait.aligned;" ::: "memory");
}

// ---------------- MLP head ---------------------------------------------------
__global__ void __launch_bounds__(256)
head_kernel(const float* __restrict__ w1, const float* __restrict__ b1,
            const float* __restrict__ w2, const float* __restrict__ b2,
            float* __restrict__ out) {
    __shared__ float hs[256];
    __shared__ float ys[100];
    const int b = blockIdx.x, tid = threadIdx.x;
    hs[tid] = g_h[0][b][tid];
    __syncthreads();
    if (tid < 100) {
        float a = b1[tid];
#pragma unroll 4
        for (int k = 0; k < 256; k++) a = fmaf(hs[k], w1[k * 100 + tid], a);
        ys[tid] = fmaxf(a, 0.f);
    }
    __syncthreads();
    if (tid == 0) {
        float s = b2[0];
        for (int j = 0; j < 100; j++) s = fmaf(ys[j], w2[j], s);
        out[b] = s;
    }
}

// ---------------- launch ------------------------------------------------------
extern "C" void kernel_launch(void* const* d_in, const int* in_sizes, int n_in,
                              void* d_out, int out_size) {
    const float* x    = (const float*)d_in[0];
    const float* kern = (const float*)d_in[1];
    const float* rk   = (const float*)d_in[2];
    const float* w1   = (const float*)d_in[3];
    const float* b1   = (const float*)d_in[4];
    const float* w2   = (const float*)d_in[5];
    const float* b2   = (const float*)d_in[6];
    float* out = (float*)d_out;

    cudaFuncSetAttribute(lstm_kernel, cudaFuncAttributeMaxDynamicSharedMemorySize,
                         SM_TOTAL);

    // order keeps ncu's capture (4th launch of cycle) on lstm_kernel
    reset_kernel<<<1, 128>>>();
    dim3 gg(8, 1024);
    xz_gemm_kernel<<<gg, 256>>>(x, kern);
    dummy_kernel<<<1, 1>>>();
    lstm_kernel<<<128, 256, SM_TOTAL>>>(rk);
    head_kernel<<<256, 256>>>(w1, b1, w2, b2, out);
}

// round 12
// speedup vs baseline: 1.8906x; 1.8906x over previous
#include <cuda_runtime.h>
#include <cstdint>

// ---------------------------------------------------------------------------
// MyModel_87522843559014: LSTM(B=256,T=512,F=128,H=256) + MLP head
//   reset -> dummy -> dummy -> xz (ncu captures 4th launch) -> lstm -> head
//   xz: tf32 mma.sync GEMM, single K=128 pass, fragment-order smem tiles.
//   lstm: R10 design (best: 3138us) — 16 groups x 8 blocks, A in registers,
//   padded flag barrier, L2 h-exchange. (R11 DSMEM exchange regressed: revert.)
// ---------------------------------------------------------------------------

typedef unsigned long long ull;

__device__ float g_xz[512u * 256u * 1024u];   // [T][B][4H] fp32
__device__ float g_h[2][256][256];            // double-buffered hidden state
__device__ unsigned g_flag[16 * 8 * 32];      // per-block flags, 128B apart

__global__ void reset_kernel() {
    if (threadIdx.x < 128) g_flag[threadIdx.x * 32] = 0u;
}
__global__ void dummy_kernel() {}

// ---------------- flag barrier (8 blocks/group, no atomics) -------------------
__device__ __forceinline__ void flag_sync(int grp, int jt, unsigned id) {
    __threadfence();               // each thread publishes its global stores
    __syncthreads();
    if (threadIdx.x == 0) {
        asm volatile("st.release.gpu.global.u32 [%0], %1;"
                     :: "l"(&g_flag[(grp * 8 + jt) * 32]), "r"(id) : "memory");
    }
    if (threadIdx.x < 8) {
        const unsigned* f = &g_flag[(grp * 8 + (int)threadIdx.x) * 32];
        unsigned v;
        do {
            asm volatile("ld.acquire.gpu.global.u32 %0, [%1];"
                         : "=r"(v) : "l"(f) : "memory");
        } while (v < id);
    }
    __syncthreads();
}

// ---------------- fast activations -------------------------------------------
__device__ __forceinline__ float sigf(float x)     { return 1.f / (1.f + __expf(-x)); }
__device__ __forceinline__ float tanhfast(float x) { return 2.f / (1.f + __expf(-2.f * x)) - 1.f; }

// ---------------- tf32 mma helpers --------------------------------------------
__device__ __forceinline__ uint32_t to_tf32(float f) {
    uint32_t u;
    asm("cvt.rna.tf32.f32 %0, %1;" : "=r"(u) : "f"(f));
    return u;
}
__device__ __forceinline__ void mma_tf32(float* c, const uint32_t* a,
                                         const uint32_t* b) {
    asm volatile(
        "mma.sync.aligned.m16n8k8.row.col.f32.tf32.tf32.f32 "
        "{%0,%1,%2,%3}, {%4,%5,%6,%7}, {%8,%9}, {%0,%1,%2,%3};"
        : "+f"(c[0]), "+f"(c[1]), "+f"(c[2]), "+f"(c[3])
        : "r"(a[0]), "r"(a[1]), "r"(a[2]), "r"(a[3]), "r"(b[0]), "r"(b[1]));
}

// ---------------- input projection GEMM (tf32 mma, single K=128 pass) ---------
// Block tile 128m x 128n, K=128. 256 threads = 8 warps; warp = 32m x 64n
// (mh = wid>>1 in 0..3, nh = wid&1). Tiles converted to fragment-order smem:
//   AF[((mh*16+km)*2+i)*32 + lane]  uint4   (4096 -> 64KB)
//   BF[((nh*16+km)*8+j)*32 + lane]  uint2   (8192 -> 64KB)
#define XZ_SMEM 131072
__global__ void __launch_bounds__(256, 1)
xz_gemm_kernel(const float* __restrict__ x, const float* __restrict__ kern) {
    extern __shared__ char smx[];
    uint4* AF = (uint4*)(smx);
    uint2* BF = (uint2*)(smx + 65536);

    const int tid = threadIdx.x;
    const int wid = tid >> 5, lane = tid & 31;
    const int gid = lane >> 2, tig = lane & 3;
    const int nb = blockIdx.x;          // 0..7
    const int mb = blockIdx.y;          // 0..1023
    const int m0 = mb * 128, n0 = nb * 128;

    // fill A fragments: A[m][k] = x[b(m)][t(m)][k], row m = t*256+b
#pragma unroll
    for (int u = 0; u < 16; u++) {
        int idx = tid + u * 256;
        int l = idx & 31, t2 = idx >> 5;
        int i = t2 & 1, km = (t2 >> 1) & 15, mh = t2 >> 5;
        int g2 = l >> 2, t4 = l & 3;
        int mr0 = m0 + mh * 32 + i * 16 + g2;
        int mr1 = mr0 + 8;
        const float* xr0 = x + ((size_t)(mr0 & 255) * 512 + (mr0 >> 8)) * 128;
        const float* xr1 = x + ((size_t)(mr1 & 255) * 512 + (mr1 >> 8)) * 128;
        int k = km * 8 + t4;
        uint4 v;
        v.x = to_tf32(xr0[k]);
        v.y = to_tf32(xr1[k]);
        v.z = to_tf32(xr0[k + 4]);
        v.w = to_tf32(xr1[k + 4]);
        AF[idx] = v;
    }
    // fill B fragments: B[n][k] = kern[k][n]
#pragma unroll
    for (int u = 0; u < 32; u++) {
        int idx = tid + u * 256;
        int l = idx & 31, t2 = idx >> 5;
        int j = t2 & 7, km = (t2 >> 3) & 15, nh = t2 >> 7;
        int n = n0 + nh * 64 + j * 8 + (l >> 2);
        int k = km * 8 + (l & 3);
        uint2 v;
        v.x = to_tf32(kern[(size_t)k * 1024 + n]);
        v.y = to_tf32(kern[(size_t)(k + 4) * 1024 + n]);
        BF[idx] = v;
    }
    __syncthreads();

    const int mh = wid >> 1, nh = wid & 1;
    const uint4* afp = AF + (mh * 16) * 2 * 32 + lane;
    const uint2* bfp = BF + (nh * 16) * 8 * 32 + lane;

    float cacc[2][8][4];
#pragma unroll
    for (int i = 0; i < 2; i++)
#pragma unroll
        for (int j = 0; j < 8; j++)
#pragma unroll
            for (int r = 0; r < 4; r++) cacc[i][j][r] = 0.f;

#pragma unroll
    for (int km = 0; km < 16; km++) {
        uint32_t a[2][4];
#pragma unroll
        for (int i = 0; i < 2; i++) {
            uint4 av = afp[(km * 2 + i) * 32];
            a[i][0] = av.x; a[i][1] = av.y; a[i][2] = av.z; a[i][3] = av.w;
        }
#pragma unroll
        for (int j = 0; j < 8; j++) {
            uint2 bv = bfp[(km * 8 + j) * 32];
            uint32_t b[2] = {bv.x, bv.y};
            mma_tf32(cacc[0][j], a[0], b);
            mma_tf32(cacc[1][j], a[1], b);
        }
    }

    // store: c0:(m,n) c1:(m,n+1) c2:(m+8,n) c3:(m+8,n+1)
#pragma unroll
    for (int i = 0; i < 2; i++) {
        int mr = m0 + mh * 32 + i * 16 + gid;
#pragma unroll
        for (int j = 0; j < 8; j++) {
            int nc = n0 + nh * 64 + j * 8 + tig * 2;
            *(float2*)&g_xz[(size_t)mr * 1024 + nc] =
                make_float2(cacc[i][j][0], cacc[i][j][1]);
            *(float2*)&g_xz[(size_t)(mr + 8) * 1024 + nc] =
                make_float2(cacc[i][j][2], cacc[i][j][3]);
        }
    }
}

// smem layout (bytes). AF (one-time A staging, 131072B) ALIASES the loop-time
// regions; A is copied to registers before BF/zs/c_s are first written.
#define SM_BF    0         // 2048 x uint2 B fragments          16384
#define SM_ZS    16384     // 4 x [128][17] f32 partials        34816
#define SM_CS    51200     // [512] f32 cell state               2048
#define SM_TOTAL 131072    // = AF staging size (max of uses)

// ---------------- persistent LSTM kernel (mma.sync tf32, A in regs) -----------
// R10 design. 16 groups x 8 blocks, 256 threads. Block: 16 batches (N) x
// 128 gate-cols (M), K=256. Warp wid: mh=wid>>2 (M half), kq=wid&3 (K quarter).
__global__ void __launch_bounds__(256, 1)
lstm_kernel(const float* __restrict__ rkernel) {
    extern __shared__ char smem[];
    uint4*  AF  = (uint4*)(smem);            // staging only (pre-loop)
    uint2*  BF  = (uint2*)(smem + SM_BF);
    float*  zs  = (float*)(smem + SM_ZS);
    float*  c_s = (float*)(smem + SM_CS);

    const int tid = threadIdx.x;
    const int wid = tid >> 5, lane = tid & 31;
    const int grp = blockIdx.x >> 3;    // 0..15
    const int jt  = blockIdx.x & 7;     // 0..7
    const int bbase = grp * 16, jbase = jt * 32;
    const int gid = lane >> 2, tig = lane & 3;

    // ---- stage A fragments in smem (fragment order), then copy to registers
    for (int idx = tid; idx < 8192; idx += 256) {
        int ln = idx & 31, t2 = idx >> 5;
        int i  = t2 & 3, km = (t2 >> 2) & 7, kqz = (t2 >> 5) & 3, mhz = t2 >> 7;
        int g2 = ln >> 2, t4 = ln & 3;
        int M0 = mhz * 64 + i * 16, K0 = kqz * 64 + km * 8;
        int mr0 = M0 + g2, mr1 = M0 + 8 + g2;
        int col0 = (mr0 >> 5) * 256 + jbase + (mr0 & 31);
        int col1 = (mr1 >> 5) * 256 + jbase + (mr1 & 31);
        uint4 v;
        v.x = to_tf32(rkernel[(K0 + t4) * 1024 + col0]);
        v.y = to_tf32(rkernel[(K0 + t4) * 1024 + col1]);
        v.z = to_tf32(rkernel[(K0 + t4 + 4) * 1024 + col0]);
        v.w = to_tf32(rkernel[(K0 + t4 + 4) * 1024 + col1]);
        AF[idx] = v;
    }
    __syncthreads();

    const int mh = wid >> 2, kq = wid & 3;
    const int Mbase = mh * 64;
    uint4 areg[4][8];
    {
        const uint4* afp = AF + (mh * 4 + kq) * 1024 + lane;
#pragma unroll
        for (int i = 0; i < 4; i++)
#pragma unroll
            for (int km = 0; km < 8; km++)
                areg[i][km] = afp[km * 128 + i * 32];
    }
    __syncthreads();   // AF region now reusable as BF/zs/c_s

    // init c=0, h0 slice = 0
    for (int p = tid; p < 512; p += 256) {
        int bb = p >> 5, jj = p & 31;
        c_s[p] = 0.f;
        g_h[0][bbase + bb][jbase + jj] = 0.f;
    }
    flag_sync(grp, jt, 1u);

    const uint2* bfp = BF + kq * 512 + lane;
    float* zq = zs + kq * (128 * 17);

    // xz prefetch registers (gate phase): [pp*4 + gate]
    float xzp[8], xzn[8];
#pragma unroll
    for (int pp = 0; pp < 2; pp++) {
        int p = tid + pp * 256;
        int bb = p >> 5, jj = p & 31;
        size_t base = ((size_t)(bbase + bb)) * 1024 + jbase + jj;
#pragma unroll
        for (int g = 0; g < 4; g++) xzp[pp * 4 + g] = __ldcg(&g_xz[base + g * 256]);
    }

    for (int t = 0; t < 512; t++) {
        const int par = t & 1;

        // B fragments: h(t) from L2, tf32, fragment order
#pragma unroll
        for (int u = 0; u < 8; u++) {
            int idx = tid + u * 256;
            int t2 = idx >> 5;
            int j = t2 & 1, km = (t2 >> 1) & 7, kqz = t2 >> 4;
            int n = j * 8 + gid;
            int k0 = kqz * 64 + km * 8 + tig;
            uint2 v;
            v.x = to_tf32(__ldcg(&g_h[par][bbase + n][k0]));
            v.y = to_tf32(__ldcg(&g_h[par][bbase + n][k0 + 4]));
            BF[idx] = v;
        }
        __syncthreads();

        // 64 MMAs, A operands from registers
        float cacc[4][2][4];
#pragma unroll
        for (int i = 0; i < 4; i++)
#pragma unroll
            for (int j = 0; j < 2; j++)
#pragma unroll
                for (int r = 0; r < 4; r++) cacc[i][j][r] = 0.f;

#pragma unroll
        for (int km = 0; km < 8; km++) {
            uint2 bv0 = bfp[km * 64];
            uint2 bv1 = bfp[km * 64 + 32];
            uint32_t b0[2] = {bv0.x, bv0.y};
            uint32_t b1[2] = {bv1.x, bv1.y};
#pragma unroll
            for (int i = 0; i < 4; i++) {
                uint32_t a[4] = {areg[i][km].x, areg[i][km].y,
                                 areg[i][km].z, areg[i][km].w};
                mma_tf32(cacc[i][0], a, b0);
                mma_tf32(cacc[i][1], a, b1);
            }
        }

        // write partials: c0:(m,n) c1:(m,n+1) c2:(m+8,n) c3:(m+8,n+1)
#pragma unroll
        for (int i = 0; i < 4; i++) {
            int m0 = Mbase + i * 16 + gid;
#pragma unroll
            for (int j = 0; j < 2; j++) {
                int n0 = j * 8 + tig * 2;
                zq[m0 * 17 + n0]           = cacc[i][j][0];
                zq[m0 * 17 + n0 + 1]       = cacc[i][j][1];
                zq[(m0 + 8) * 17 + n0]     = cacc[i][j][2];
                zq[(m0 + 8) * 17 + n0 + 1] = cacc[i][j][3];
            }
        }

        // prefetch next xz (independent of h -> off critical path)
        if (t < 511) {
#pragma unroll
            for (int pp = 0; pp < 2; pp++) {
                int p = tid + pp * 256;
                int bb = p >> 5, jj = p & 31;
                size_t base = ((size_t)((t + 1) * 256 + bbase + bb)) * 1024
                            + jbase + jj;
#pragma unroll
                for (int g = 0; g < 4; g++)
                    xzn[pp * 4 + g] = __ldcg(&g_xz[base + g * 256]);
            }
        }
        __syncthreads();

        // gates: 512 (b,j) pairs, 2 per thread; sum 4 k-quarter partials + xz
#pragma unroll
        for (int pp = 0; pp < 2; pp++) {
            int p = tid + pp * 256;
            int bb = p >> 5, jj = p & 31;
            float zi = xzp[pp * 4 + 0], zf = xzp[pp * 4 + 1];
            float zg = xzp[pp * 4 + 2], zo = xzp[pp * 4 + 3];
#pragma unroll
            for (int q = 0; q < 4; q++) {
                const float* zb = zs + q * (128 * 17);
                zi += zb[(jj)      * 17 + bb];
                zf += zb[(32 + jj) * 17 + bb];
                zg += zb[(64 + jj) * 17 + bb];
                zo += zb[(96 + jj) * 17 + bb];
            }
            float cn = sigf(zf) * c_s[p] + sigf(zi) * tanhfast(zg);
            c_s[p] = cn;
            g_h[par ^ 1][bbase + bb][jbase + jj] = sigf(zo) * tanhfast(cn);
        }
#pragma unroll
        for (int r = 0; r < 8; r++) xzp[r] = xzn[r];

        if (t < 511) flag_sync(grp, jt, (unsigned)(t + 2));
    }
    // final h in g_h[0] (512 even); kernel boundary syncs before head
}

// ---------------- MLP head ---------------------------------------------------
__global__ void __launch_bounds__(256)
head_kernel(const float* __restrict__ w1, const float* __restrict__ b1,
            const float* __restrict__ w2, const float* __restrict__ b2,
            float* __restrict__ out) {
    __shared__ float hs[256];
    __shared__ float ys[100];
    const int b = blockIdx.x, tid = threadIdx.x;
    hs[tid] = g_h[0][b][tid];
    __syncthreads();
    if (tid < 100) {
        float a = b1[tid];
#pragma unroll 4
        for (int k = 0; k < 256; k++) a = fmaf(hs[k], w1[k * 100 + tid], a);
        ys[tid] = fmaxf(a, 0.f);
    }
    __syncthreads();
    if (tid == 0) {
        float s = b2[0];
        for (int j = 0; j < 100; j++) s = fmaf(ys[j], w2[j], s);
        out[b] = s;
    }
}

// ---------------- launch ------------------------------------------------------
extern "C" void kernel_launch(void* const* d_in, const int* in_sizes, int n_in,
                              void* d_out, int out_size) {
    const float* x    = (const float*)d_in[0];
    const float* kern = (const float*)d_in[1];
    const float* rk   = (const float*)d_in[2];
    const float* w1   = (const float*)d_in[3];
    const float* b1   = (const float*)d_in[4];
    const float* w2   = (const float*)d_in[5];
    const float* b2   = (const float*)d_in[6];
    float* out = (float*)d_out;

    cudaFuncSetAttribute(xz_gemm_kernel, cudaFuncAttributeMaxDynamicSharedMemorySize,
                         XZ_SMEM);
    cudaFuncSetAttribute(lstm_kernel, cudaFuncAttributeMaxDynamicSharedMemorySize,
                         SM_TOTAL);

    // order puts ncu's capture (4th launch of cycle) on the NEW xz kernel
    reset_kernel<<<1, 128>>>();
    dummy_kernel<<<1, 1>>>();
    dummy_kernel<<<1, 1>>>();
    dim3 gg(8, 1024);
    xz_gemm_kernel<<<gg, 256, XZ_SMEM>>>(x, kern);
    lstm_kernel<<<128, 256, SM_TOTAL>>>(rk);
    head_kernel<<<256, 256>>>(w1, b1, w2, b2, out);
}